// round 1
// baseline (speedup 1.0000x reference)
#include <cuda_runtime.h>
#include <math.h>

// Problem constants
#define BATCH 4
#define CH    32
#define SEQ   (BATCH*CH)     // 128 independent length-N sequences
#define HH    128            // input H=W
#define P     130            // padded side (128 + 2*1)
#define NTOT  (P*P)          // 16900 = FFT length
#define OCH   32

#ifndef M_PI
#define M_PI 3.14159265358979323846
#endif

// Scratch (device globals; no allocation allowed)
__device__ float2 g_twN[NTOT];          // e^{-2pi i j / 16900}
__device__ float2 g_tw130[P];           // e^{-2pi i j / 130}
__device__ float2 g_buf1[SEQ * NTOT];   // Bm (fwd col-FFT * twiddle), then Cm (inv row-FFT * twiddle)
__device__ float2 g_buf2[SEQ * NTOT];   // X (thresholded spectrum)
__device__ float  g_xp[SEQ * NTOT];     // x' (denoised padded image)

// ---------------------------------------------------------------------------
// Twiddle tables (computed in double each launch; deterministic)
__global__ void k_init() {
    int j = blockIdx.x * blockDim.x + threadIdx.x;
    if (j < NTOT) {
        double a = -2.0 * M_PI * (double)j / (double)NTOT;
        double s, c; sincos(a, &s, &c);
        g_twN[j] = make_float2((float)c, (float)s);
    }
    if (j < P) {
        double a = -2.0 * M_PI * (double)j / (double)P;
        double s, c; sincos(a, &s, &c);
        g_tw130[j] = make_float2((float)c, (float)s);
    }
}

// ---------------------------------------------------------------------------
// K1: zero-pad + forward column FFT over n1 + twiddle by e^{-2pi i n2 k1/N}
// Bm[seq][k1][n2] = (sum_{n1=1..128} x[n1-1][n2-1] * tw130[(n1*k1)%130]) * twN[n2*k1]
// grid (17, SEQ), block 130 (thread = n2), 8 k1 per block
__global__ void k_colfft(const float* __restrict__ x) {
    __shared__ float2 twk[8][P];
    const int seq  = blockIdx.y;
    const int k1_0 = blockIdx.x * 8;
    const int n2   = threadIdx.x;            // 0..129

    #pragma unroll
    for (int kl = 0; kl < 8; kl++) {
        int k1m = (k1_0 + kl) % P;
        twk[kl][n2] = g_tw130[(n2 * k1m) % P];   // filled with n1 := n2 role
    }
    __syncthreads();

    float2 acc[8];
    #pragma unroll
    for (int kl = 0; kl < 8; kl++) acc[kl] = make_float2(0.f, 0.f);

    const float* xs = x + seq * HH * HH;
    const bool interior = (n2 >= 1 && n2 <= HH);

    for (int n1 = 1; n1 <= HH; n1++) {
        float xv = interior ? xs[(n1 - 1) * HH + (n2 - 1)] : 0.f;
        #pragma unroll
        for (int kl = 0; kl < 8; kl++) {
            float2 t = twk[kl][n1];
            acc[kl].x = fmaf(xv, t.x, acc[kl].x);
            acc[kl].y = fmaf(xv, t.y, acc[kl].y);
        }
    }

    #pragma unroll
    for (int kl = 0; kl < 8; kl++) {
        int k1 = k1_0 + kl;
        if (k1 < P) {
            float2 T = g_twN[n2 * k1];   // n2*k1 <= 129*129 < 16900
            float2 b;
            b.x = acc[kl].x * T.x - acc[kl].y * T.y;
            b.y = acc[kl].x * T.y + acc[kl].y * T.x;
            g_buf1[(seq * P + k1) * P + n2] = b;
        }
    }
}

// ---------------------------------------------------------------------------
// K2: forward row FFT over n2 + threshold
// X[k1][k2] = sum_{n2} Bm[k1][n2] * tw130[(n2*k2)%130];  zero if |Re| < 0.01
// grid (65, SEQ), block (130,2): thread = k2, threadIdx.y selects k1 row
__global__ void k_rowfft_thresh() {
    __shared__ float2 row[2][P];
    __shared__ float2 tws[P];
    const int seq = blockIdx.y;
    const int k1  = blockIdx.x * 2 + threadIdx.y;
    const int k2  = threadIdx.x;

    int t = threadIdx.y * P + threadIdx.x;
    if (t < P) tws[t] = g_tw130[t];
    row[threadIdx.y][k2] = g_buf1[(seq * P + k1) * P + k2];
    __syncthreads();

    float2 acc = make_float2(0.f, 0.f);
    int idx = 0;
    #pragma unroll 5
    for (int n2 = 0; n2 < P; n2++) {
        float2 Bv = row[threadIdx.y][n2];
        float2 tt = tws[idx];
        acc.x = fmaf(Bv.x, tt.x, acc.x);
        acc.x = fmaf(-Bv.y, tt.y, acc.x);
        acc.y = fmaf(Bv.x, tt.y, acc.y);
        acc.y = fmaf(Bv.y, tt.x, acc.y);
        idx += k2; if (idx >= P) idx -= P;
    }
    if (fabsf(acc.x) < 0.01f) acc = make_float2(0.f, 0.f);
    g_buf2[(seq * P + k1) * P + k2] = acc;
}

// ---------------------------------------------------------------------------
// K3: inverse row FFT over k2 + conj twiddle
// Cm[k1][n2] = (sum_{k2} X[k1][k2] * conj(tw130[(n2*k2)%130])) * conj(twN[n2*k1])
// grid (65, SEQ), block (130,2): thread = n2
__global__ void k_rowifft() {
    __shared__ float2 row[2][P];
    __shared__ float2 tws[P];
    const int seq = blockIdx.y;
    const int k1  = blockIdx.x * 2 + threadIdx.y;
    const int n2  = threadIdx.x;

    int t = threadIdx.y * P + threadIdx.x;
    if (t < P) tws[t] = g_tw130[t];
    row[threadIdx.y][n2] = g_buf2[(seq * P + k1) * P + n2];
    __syncthreads();

    float2 acc = make_float2(0.f, 0.f);
    int idx = 0;
    #pragma unroll 5
    for (int k2 = 0; k2 < P; k2++) {
        float2 Xv = row[threadIdx.y][k2];
        float2 tt = tws[idx];
        // multiply by conj(tt): (tt.x, -tt.y) -> e^{+i theta}
        acc.x = fmaf(Xv.x, tt.x, acc.x);
        acc.x = fmaf(Xv.y, tt.y, acc.x);
        acc.y = fmaf(Xv.y, tt.x, acc.y);
        acc.y = fmaf(-Xv.x, tt.y, acc.y);
        idx += n2; if (idx >= P) idx -= P;
    }
    float2 T = g_twN[n2 * k1];  // conj applied below
    float2 c;
    c.x = acc.x * T.x + acc.y * T.y;
    c.y = acc.y * T.x - acc.x * T.y;
    g_buf1[(seq * P + k1) * P + n2] = c;
}

// ---------------------------------------------------------------------------
// K4: inverse column FFT over k1, real part only, scale 1/N
// x'[n1][n2] = (1/N) * sum_{k1} Re( Cm[k1][n2] * e^{+2pi i n1 k1/130} )
//            = (1/N) * sum_{k1} (C.re*t.re + C.im*t.im), t = tw130[(n1*k1)%130]
// grid (17, SEQ), block 130 (thread = n2), 8 n1 per block
__global__ void k_colifft() {
    __shared__ float2 twk[8][P];
    const int seq  = blockIdx.y;
    const int n1_0 = blockIdx.x * 8;
    const int n2   = threadIdx.x;

    #pragma unroll
    for (int nl = 0; nl < 8; nl++) {
        int n1m = (n1_0 + nl) % P;
        twk[nl][n2] = g_tw130[(n2 * n1m) % P];  // filled with k1 := n2 role
    }
    __syncthreads();

    float acc[8];
    #pragma unroll
    for (int nl = 0; nl < 8; nl++) acc[nl] = 0.f;

    const float2* Crow = g_buf1 + seq * NTOT;
    for (int k1 = 0; k1 < P; k1++) {
        float2 Cv = Crow[k1 * P + n2];
        #pragma unroll
        for (int nl = 0; nl < 8; nl++) {
            float2 tt = twk[nl][k1];
            acc[nl] = fmaf(Cv.x, tt.x, acc[nl]);
            acc[nl] = fmaf(Cv.y, tt.y, acc[nl]);
        }
    }

    const float invN = 1.0f / (float)NTOT;
    #pragma unroll
    for (int nl = 0; nl < 8; nl++) {
        int n1 = n1_0 + nl;
        if (n1 < P) g_xp[(seq * P + n1) * P + n2] = acc[nl] * invN;
    }
}

// ---------------------------------------------------------------------------
// K5: dense 3x3 cross-correlation on x' (valid on the 130x130 grid) + bias
// out[b][o][i][j] = bias[o] + sum_c sum_{r,s} w[o][c][r][s] * x'[b*32+c][i+r][j+s]
// grid (128 i, 4 b), block 128 (thread = j); all 32 o accumulated in registers
__global__ void k_conv(const float* __restrict__ w,
                       const float* __restrict__ bias,
                       float* __restrict__ out) {
    __shared__ float rows[3][P];
    __shared__ float wsm[9][OCH];   // [rs][o], rows 128B -> float4 friendly
    const int i = blockIdx.x;
    const int b = blockIdx.y;
    const int j = threadIdx.x;

    float acc[OCH];
    #pragma unroll
    for (int o = 0; o < OCH; o++) acc[o] = 0.f;

    for (int c = 0; c < CH; c++) {
        __syncthreads();
        const float* xp = g_xp + ((b * CH + c) * P + i) * P;
        for (int t = j; t < 3 * P; t += 128) {
            int r = t / P, col = t % P;
            rows[r][col] = xp[r * P + col];
        }
        for (int t = j; t < OCH * 9; t += 128) {
            int o = t / 9, rs = t % 9;
            wsm[rs][o] = w[(o * CH + c) * 9 + rs];
        }
        __syncthreads();

        float xv[9];
        #pragma unroll
        for (int r = 0; r < 3; r++)
            #pragma unroll
            for (int s = 0; s < 3; s++)
                xv[r * 3 + s] = rows[r][j + s];

        #pragma unroll
        for (int rs = 0; rs < 9; rs++) {
            float xr = xv[rs];
            #pragma unroll
            for (int og = 0; og < OCH / 4; og++) {
                float4 w4 = *reinterpret_cast<const float4*>(&wsm[rs][og * 4]);
                acc[og * 4 + 0] = fmaf(w4.x, xr, acc[og * 4 + 0]);
                acc[og * 4 + 1] = fmaf(w4.y, xr, acc[og * 4 + 1]);
                acc[og * 4 + 2] = fmaf(w4.z, xr, acc[og * 4 + 2]);
                acc[og * 4 + 3] = fmaf(w4.w, xr, acc[og * 4 + 3]);
            }
        }
    }

    #pragma unroll
    for (int o = 0; o < OCH; o++) {
        out[((b * OCH + o) * HH + i) * HH + j] = acc[o] + __ldg(&bias[o]);
    }
}

// ---------------------------------------------------------------------------
extern "C" void kernel_launch(void* const* d_in, const int* in_sizes, int n_in,
                              void* d_out, int out_size) {
    const float* x  = nullptr;
    const float* w  = nullptr;
    const float* bs = nullptr;
    for (int i = 0; i < n_in; i++) {
        if (in_sizes[i] == BATCH * CH * HH * HH)      x  = (const float*)d_in[i];
        else if (in_sizes[i] == OCH * CH * 3 * 3)     w  = (const float*)d_in[i];
        else if (in_sizes[i] == OCH)                  bs = (const float*)d_in[i];
    }
    float* out = (float*)d_out;

    k_init<<<(NTOT + 255) / 256, 256>>>();
    k_colfft<<<dim3(17, SEQ), 130>>>(x);
    k_rowfft_thresh<<<dim3(65, SEQ), dim3(130, 2)>>>();
    k_rowifft<<<dim3(65, SEQ), dim3(130, 2)>>>();
    k_colifft<<<dim3(17, SEQ), 130>>>();
    k_conv<<<dim3(HH, BATCH), HH>>>(w, bs, out);
}

// round 2
// speedup vs baseline: 2.4319x; 2.4319x over previous
#include <cuda_runtime.h>
#include <math.h>

// Problem constants
#define BATCH 4
#define CH    32
#define SEQ   (BATCH*CH)     // 128 independent length-N sequences
#define HH    128            // input H=W
#define P     130            // padded side (128 + 2*1)
#define NTOT  (P*P)          // 16900 = FFT length
#define OCH   32
#define RH    66             // Hermitian-half rows: k1 = 0..65

#ifndef M_PI
#define M_PI 3.14159265358979323846
#endif

// Scratch (device globals; no allocation allowed)
__device__ float2 g_twN[NTOT];            // e^{-2pi i j / 16900}
__device__ float2 g_tw130[P];             // e^{-2pi i j / 130}
__device__ float2 g_buf1[SEQ * RH * P];   // Bm (fwd), then Cm (post row-IFFT, rows 1..64 pre-scaled x2)
__device__ float2 g_buf2[SEQ * RH * P];   // X (thresholded spectrum), rows 0..65
__device__ float  g_xp[SEQ * NTOT];       // x' (denoised padded image)

// ---------------------------------------------------------------------------
__global__ void k_init() {
    int j = blockIdx.x * blockDim.x + threadIdx.x;
    if (j < NTOT) {
        double a = -2.0 * M_PI * (double)j / (double)NTOT;
        double s, c; sincos(a, &s, &c);
        g_twN[j] = make_float2((float)c, (float)s);
    }
    if (j < P) {
        double a = -2.0 * M_PI * (double)j / (double)P;
        double s, c; sincos(a, &s, &c);
        g_tw130[j] = make_float2((float)c, (float)s);
    }
}

// ---------------------------------------------------------------------------
// K1: zero-pad + forward column FFT over n1 + cross twiddle. Rows k1=0..65 only.
// Bm[seq][k1][n2] = (sum_{n1=1..128} x[n1-1][n2-1] * tw130[(n1*k1)%130]) * twN[n2*k1]
// grid (11, SEQ), block 130 (thread = n2), 6 k1 per block (66 = 6*11)
#define KL1 6
__global__ void k_colfft(const float* __restrict__ x) {
    __shared__ float2 twk[KL1][P];
    const int seq  = blockIdx.y;
    const int k1_0 = blockIdx.x * KL1;
    const int n2   = threadIdx.x;            // 0..129

    #pragma unroll
    for (int kl = 0; kl < KL1; kl++) {
        int k1 = k1_0 + kl;                  // < 66 < 130, no outer mod needed
        twk[kl][n2] = g_tw130[(n2 * k1) % P];
    }
    __syncthreads();

    float2 acc[KL1];
    #pragma unroll
    for (int kl = 0; kl < KL1; kl++) acc[kl] = make_float2(0.f, 0.f);

    const float* xs = x + seq * HH * HH;
    const bool interior = (n2 >= 1 && n2 <= HH);

    for (int n1 = 1; n1 <= HH; n1++) {
        float xv = interior ? xs[(n1 - 1) * HH + (n2 - 1)] : 0.f;
        #pragma unroll
        for (int kl = 0; kl < KL1; kl++) {
            float2 t = twk[kl][n1];
            acc[kl].x = fmaf(xv, t.x, acc[kl].x);
            acc[kl].y = fmaf(xv, t.y, acc[kl].y);
        }
    }

    #pragma unroll
    for (int kl = 0; kl < KL1; kl++) {
        int k1 = k1_0 + kl;
        float2 T = g_twN[n2 * k1];   // n2*k1 <= 129*65 < 16900
        float2 b;
        b.x = acc[kl].x * T.x - acc[kl].y * T.y;
        b.y = acc[kl].x * T.y + acc[kl].y * T.x;
        g_buf1[(seq * RH + k1) * P + n2] = b;
    }
}

// ---------------------------------------------------------------------------
// K2: forward row FFT over n2 + threshold. Rows k1=0..65.
// X[k1][k2] = sum_{n2} Bm[k1][n2] * tw130[(n2*k2)%130];  zero if |Re| < 0.01
// grid (11, SEQ), block 130 (thread = k2), 6 rows per block
#define R2 6
__global__ void k_rowfft_thresh() {
    __shared__ float2 rows[R2][P];
    __shared__ float2 tws[P];
    const int seq  = blockIdx.y;
    const int k1_0 = blockIdx.x * R2;
    const int k2   = threadIdx.x;

    tws[k2] = g_tw130[k2];
    const float2* src = g_buf1 + (seq * RH + k1_0) * P;
    #pragma unroll
    for (int r = 0; r < R2; r++) rows[r][k2] = src[r * P + k2];
    __syncthreads();

    float2 acc[R2];
    #pragma unroll
    for (int r = 0; r < R2; r++) acc[r] = make_float2(0.f, 0.f);

    int idx = 0;
    for (int n2 = 0; n2 < P; n2++) {
        float2 tt = tws[idx];
        idx += k2; if (idx >= P) idx -= P;
        #pragma unroll
        for (int r = 0; r < R2; r++) {
            float2 Bv = rows[r][n2];
            acc[r].x = fmaf(Bv.x, tt.x, acc[r].x);
            acc[r].x = fmaf(-Bv.y, tt.y, acc[r].x);
            acc[r].y = fmaf(Bv.x, tt.y, acc[r].y);
            acc[r].y = fmaf(Bv.y, tt.x, acc[r].y);
        }
    }

    float2* dst = g_buf2 + (seq * RH + k1_0) * P;
    #pragma unroll
    for (int r = 0; r < R2; r++) {
        float2 v = acc[r];
        if (fabsf(v.x) < 0.01f) v = make_float2(0.f, 0.f);
        dst[r * P + k2] = v;
    }
}

// ---------------------------------------------------------------------------
// K3: inverse row FFT over k2 + conj cross twiddle. Rows k1=0..65.
// Cm[k1][n2] = (sum_{k2} X[k1][k2] * conj(tw130[(n2*k2)%130])) * conj(twN[n2*k1])
// Rows 1..64 are pre-scaled by 2 (Hermitian fold for K4).
// grid (11, SEQ), block 130 (thread = n2), 6 rows per block
__global__ void k_rowifft() {
    __shared__ float2 rows[R2][P];
    __shared__ float2 tws[P];
    const int seq  = blockIdx.y;
    const int k1_0 = blockIdx.x * R2;
    const int n2   = threadIdx.x;

    tws[n2] = g_tw130[n2];
    const float2* src = g_buf2 + (seq * RH + k1_0) * P;
    #pragma unroll
    for (int r = 0; r < R2; r++) rows[r][n2] = src[r * P + n2];
    __syncthreads();

    float2 acc[R2];
    #pragma unroll
    for (int r = 0; r < R2; r++) acc[r] = make_float2(0.f, 0.f);

    int idx = 0;
    for (int k2 = 0; k2 < P; k2++) {
        float2 tt = tws[idx];          // multiply by conj(tt) = e^{+i}
        idx += n2; if (idx >= P) idx -= P;
        #pragma unroll
        for (int r = 0; r < R2; r++) {
            float2 Xv = rows[r][k2];
            acc[r].x = fmaf(Xv.x, tt.x, acc[r].x);
            acc[r].x = fmaf(Xv.y, tt.y, acc[r].x);
            acc[r].y = fmaf(Xv.y, tt.x, acc[r].y);
            acc[r].y = fmaf(-Xv.x, tt.y, acc[r].y);
        }
    }

    float2* dst = g_buf1 + (seq * RH + k1_0) * P;
    #pragma unroll
    for (int r = 0; r < R2; r++) {
        int k1 = k1_0 + r;
        float2 T = g_twN[n2 * k1];     // apply conj(T)
        float sc = (k1 >= 1 && k1 <= 64) ? 2.0f : 1.0f;
        float2 c;
        c.x = (acc[r].x * T.x + acc[r].y * T.y) * sc;
        c.y = (acc[r].y * T.x - acc[r].x * T.y) * sc;
        dst[r * P + n2] = c;
    }
}

// ---------------------------------------------------------------------------
// K4: inverse column FFT over k1 (folded: 66 terms), real part, scale 1/N
// x'[n1][n2] = (1/N) * sum_{k1=0..65} sc(k1) * (C.re*t.re + C.im*t.im),
//   t = tw130[(n1*k1)%130], sc already baked into Cm by K3.
// grid (10, SEQ), block 130 (thread = n2), 13 n1 per block (130 = 13*10)
#define NL4 13
__global__ void k_colifft() {
    __shared__ float2 twk[NL4][P];     // only [0..65] used in loop; fill all for simplicity
    const int seq  = blockIdx.y;
    const int n1_0 = blockIdx.x * NL4;
    const int n2   = threadIdx.x;

    #pragma unroll
    for (int nl = 0; nl < NL4; nl++) {
        int n1 = n1_0 + nl;            // < 130
        twk[nl][n2] = g_tw130[(n2 * n1) % P];   // indexed later by k1 in thread-uniform way
    }
    __syncthreads();

    float acc[NL4];
    #pragma unroll
    for (int nl = 0; nl < NL4; nl++) acc[nl] = 0.f;

    const float2* Crow = g_buf1 + seq * RH * P;
    for (int k1 = 0; k1 < RH; k1++) {
        float2 Cv = Crow[k1 * P + n2];
        #pragma unroll
        for (int nl = 0; nl < NL4; nl++) {
            float2 tt = twk[nl][k1];
            acc[nl] = fmaf(Cv.x, tt.x, acc[nl]);
            acc[nl] = fmaf(Cv.y, tt.y, acc[nl]);
        }
    }

    const float invN = 1.0f / (float)NTOT;
    #pragma unroll
    for (int nl = 0; nl < NL4; nl++) {
        int n1 = n1_0 + nl;
        g_xp[(seq * P + n1) * P + n2] = acc[nl] * invN;
    }
}

// ---------------------------------------------------------------------------
// K5: dense 3x3 cross-correlation on x' (valid on the 130x130 grid) + bias
__global__ void k_conv(const float* __restrict__ w,
                       const float* __restrict__ bias,
                       float* __restrict__ out) {
    __shared__ float rows[3][P];
    __shared__ float wsm[9][OCH];
    const int i = blockIdx.x;
    const int b = blockIdx.y;
    const int j = threadIdx.x;

    float acc[OCH];
    #pragma unroll
    for (int o = 0; o < OCH; o++) acc[o] = 0.f;

    for (int c = 0; c < CH; c++) {
        __syncthreads();
        const float* xp = g_xp + ((b * CH + c) * P + i) * P;
        for (int t = j; t < 3 * P; t += 128) {
            int r = t / P, col = t % P;
            rows[r][col] = xp[r * P + col];
        }
        for (int t = j; t < OCH * 9; t += 128) {
            int o = t / 9, rs = t % 9;
            wsm[rs][o] = w[(o * CH + c) * 9 + rs];
        }
        __syncthreads();

        float xv[9];
        #pragma unroll
        for (int r = 0; r < 3; r++)
            #pragma unroll
            for (int s = 0; s < 3; s++)
                xv[r * 3 + s] = rows[r][j + s];

        #pragma unroll
        for (int rs = 0; rs < 9; rs++) {
            float xr = xv[rs];
            #pragma unroll
            for (int og = 0; og < OCH / 4; og++) {
                float4 w4 = *reinterpret_cast<const float4*>(&wsm[rs][og * 4]);
                acc[og * 4 + 0] = fmaf(w4.x, xr, acc[og * 4 + 0]);
                acc[og * 4 + 1] = fmaf(w4.y, xr, acc[og * 4 + 1]);
                acc[og * 4 + 2] = fmaf(w4.z, xr, acc[og * 4 + 2]);
                acc[og * 4 + 3] = fmaf(w4.w, xr, acc[og * 4 + 3]);
            }
        }
    }

    #pragma unroll
    for (int o = 0; o < OCH; o++) {
        out[((b * OCH + o) * HH + i) * HH + j] = acc[o] + __ldg(&bias[o]);
    }
}

// ---------------------------------------------------------------------------
extern "C" void kernel_launch(void* const* d_in, const int* in_sizes, int n_in,
                              void* d_out, int out_size) {
    const float* x  = nullptr;
    const float* w  = nullptr;
    const float* bs = nullptr;
    for (int i = 0; i < n_in; i++) {
        if (in_sizes[i] == BATCH * CH * HH * HH)      x  = (const float*)d_in[i];
        else if (in_sizes[i] == OCH * CH * 3 * 3)     w  = (const float*)d_in[i];
        else if (in_sizes[i] == OCH)                  bs = (const float*)d_in[i];
    }
    float* out = (float*)d_out;

    k_init<<<(NTOT + 255) / 256, 256>>>();
    k_colfft<<<dim3(11, SEQ), P>>>(x);
    k_rowfft_thresh<<<dim3(11, SEQ), P>>>();
    k_rowifft<<<dim3(11, SEQ), P>>>();
    k_colifft<<<dim3(10, SEQ), P>>>();
    k_conv<<<dim3(HH, BATCH), HH>>>(w, bs, out);
}

// round 3
// speedup vs baseline: 3.1453x; 1.2934x over previous
#include <cuda_runtime.h>
#include <math.h>

// Problem constants
#define BATCH 4
#define CH    32
#define SEQ   (BATCH*CH)     // 128 independent length-N sequences
#define HH    128            // input H=W
#define P     130            // padded side (128 + 2*1)
#define NTOT  (P*P)          // 16900 = FFT length
#define OCH   32
#define RH    66             // Hermitian-half rows: k1 = 0..65

#ifndef M_PI
#define M_PI 3.14159265358979323846
#endif

// Scratch (device globals; no allocation allowed)
__device__ float2 g_twN[NTOT];            // e^{-2pi i j / 16900}
__device__ float2 g_tw130[P];             // e^{-2pi i j / 130}
__device__ float2 g_buf1[SEQ * RH * P];   // Bm (fwd), then Cm (post row-IFFT, rows 1..64 pre-scaled x2)
__device__ float2 g_buf2[SEQ * RH * P];   // X (thresholded spectrum), rows 0..65
__device__ float  g_xp[SEQ * NTOT];       // x' (denoised padded image)

// ---------------------------------------------------------------------------
__global__ void k_init() {
    int j = blockIdx.x * blockDim.x + threadIdx.x;
    if (j < NTOT) {
        double a = -2.0 * M_PI * (double)j / (double)NTOT;
        double s, c; sincos(a, &s, &c);
        g_twN[j] = make_float2((float)c, (float)s);
    }
    if (j < P) {
        double a = -2.0 * M_PI * (double)j / (double)P;
        double s, c; sincos(a, &s, &c);
        g_tw130[j] = make_float2((float)c, (float)s);
    }
}

// ---------------------------------------------------------------------------
// K1: zero-pad + forward column FFT over n1 + cross twiddle. Rows k1=0..65 only.
// Bm[seq][k1][n2] = (sum_{n1=1..128} x[n1-1][n2-1] * tw130[(n1*k1)%130]) * twN[n2*k1]
// grid (11, SEQ), block 130 (thread = n2), 6 k1 per block; n1-loop unrolled x2
// with float4 twiddle-pair loads.
#define KL1 6
__global__ void k_colfft(const float* __restrict__ x) {
    __shared__ float2 twk[KL1][128];         // twk[kl][i] = tw130[((i+1)*k1)%130]
    const int seq  = blockIdx.y;
    const int k1_0 = blockIdx.x * KL1;
    const int n2   = threadIdx.x;            // 0..129

    if (n2 < 128) {
        #pragma unroll
        for (int kl = 0; kl < KL1; kl++) {
            int k1 = k1_0 + kl;
            twk[kl][n2] = g_tw130[((n2 + 1) * k1) % P];
        }
    }
    __syncthreads();

    float2 acc[KL1];
    #pragma unroll
    for (int kl = 0; kl < KL1; kl++) acc[kl] = make_float2(0.f, 0.f);

    const float* xs = x + seq * HH * HH;
    const bool interior = (n2 >= 1 && n2 <= HH);

    for (int i = 0; i < 128; i += 2) {       // n1 = i+1, i+2
        float xv0 = interior ? __ldg(&xs[i * HH + (n2 - 1)]) : 0.f;
        float xv1 = interior ? __ldg(&xs[(i + 1) * HH + (n2 - 1)]) : 0.f;
        #pragma unroll
        for (int kl = 0; kl < KL1; kl++) {
            float4 tp = *reinterpret_cast<const float4*>(&twk[kl][i]);
            acc[kl].x = fmaf(xv0, tp.x, acc[kl].x);
            acc[kl].y = fmaf(xv0, tp.y, acc[kl].y);
            acc[kl].x = fmaf(xv1, tp.z, acc[kl].x);
            acc[kl].y = fmaf(xv1, tp.w, acc[kl].y);
        }
    }

    #pragma unroll
    for (int kl = 0; kl < KL1; kl++) {
        int k1 = k1_0 + kl;
        float2 T = g_twN[n2 * k1];   // n2*k1 <= 129*65 < 16900
        float2 b;
        b.x = acc[kl].x * T.x - acc[kl].y * T.y;
        b.y = acc[kl].x * T.y + acc[kl].y * T.x;
        g_buf1[(seq * RH + k1) * P + n2] = b;
    }
}

// ---------------------------------------------------------------------------
// K2: forward row FFT over n2 (radix 13x10 Cooley-Tukey) + threshold.
// n2 = 13a + b:  G[b][r] = sum_a B[13a+b] * w10[(a*r)%10]   (r = k2 mod 10)
//                X[k2]   = sum_b G[b][k2%10] * tw130[(b*k2)%130]
// grid (11, SEQ), block 130, 6 rows per block
#define R2 6
__global__ void k_rowfft_thresh() {
    __shared__ float2 Brow[R2][P];
    __shared__ float2 G[R2][P];      // G[row][b*10+r]
    __shared__ float2 tws[P];
    __shared__ float2 w10[10];
    const int seq  = blockIdx.y;
    const int k1_0 = blockIdx.x * R2;
    const int t    = threadIdx.x;    // 0..129

    tws[t] = g_tw130[t];
    if (t < 10) w10[t] = g_tw130[13 * t];
    const float2* src = g_buf1 + (seq * RH + k1_0) * P;
    #pragma unroll
    for (int r = 0; r < R2; r++) Brow[r][t] = src[r * P + t];
    __syncthreads();

    // Stage 1: thread t -> (b = t/10, rr = t%10)
    {
        const int b  = t / 10;
        const int rr = t - b * 10;
        float2 acc[R2];
        #pragma unroll
        for (int r = 0; r < R2; r++) acc[r] = make_float2(0.f, 0.f);
        int m = 0;
        #pragma unroll
        for (int a = 0; a < 10; a++) {
            float2 w = w10[m];
            m += rr; if (m >= 10) m -= 10;
            int si = 13 * a + b;
            #pragma unroll
            for (int r = 0; r < R2; r++) {
                float2 Bv = Brow[r][si];
                acc[r].x = fmaf(Bv.x, w.x, acc[r].x);
                acc[r].x = fmaf(-Bv.y, w.y, acc[r].x);
                acc[r].y = fmaf(Bv.x, w.y, acc[r].y);
                acc[r].y = fmaf(Bv.y, w.x, acc[r].y);
            }
        }
        #pragma unroll
        for (int r = 0; r < R2; r++) G[r][t] = acc[r];
    }
    __syncthreads();

    // Stage 2: thread t = k2
    {
        const int k2 = t;
        const int r0 = k2 % 10;
        float2 acc[R2];
        #pragma unroll
        for (int r = 0; r < R2; r++) acc[r] = make_float2(0.f, 0.f);
        int idx = 0;
        #pragma unroll
        for (int b = 0; b < 13; b++) {
            float2 tt = tws[idx];
            idx += k2; if (idx >= P) idx -= P;
            int gi = b * 10 + r0;
            #pragma unroll
            for (int r = 0; r < R2; r++) {
                float2 Gv = G[r][gi];
                acc[r].x = fmaf(Gv.x, tt.x, acc[r].x);
                acc[r].x = fmaf(-Gv.y, tt.y, acc[r].x);
                acc[r].y = fmaf(Gv.x, tt.y, acc[r].y);
                acc[r].y = fmaf(Gv.y, tt.x, acc[r].y);
            }
        }
        float2* dst = g_buf2 + (seq * RH + k1_0) * P;
        #pragma unroll
        for (int r = 0; r < R2; r++) {
            float2 v = acc[r];
            if (fabsf(v.x) < 0.01f) v = make_float2(0.f, 0.f);
            dst[r * P + k2] = v;
        }
    }
}

// ---------------------------------------------------------------------------
// K3: inverse row FFT over k2 (radix 13x10, conj twiddles) + conj cross twiddle.
// k2 = 13a + b:  G[b][r] = sum_a X[13a+b] * conj(w10[(a*r)%10])  (r = n2 mod 10)
//                Cm[n2]  = (sum_b G[b][n2%10] * conj(tw130[(b*n2)%130])) * conj(twN[n2*k1])
// Rows 1..64 pre-scaled by 2 (Hermitian fold for K4).
// grid (11, SEQ), block 130, 6 rows per block
__global__ void k_rowifft() {
    __shared__ float2 Xrow[R2][P];
    __shared__ float2 G[R2][P];
    __shared__ float2 tws[P];
    __shared__ float2 w10[10];
    const int seq  = blockIdx.y;
    const int k1_0 = blockIdx.x * R2;
    const int t    = threadIdx.x;

    tws[t] = g_tw130[t];
    if (t < 10) w10[t] = g_tw130[13 * t];
    const float2* src = g_buf2 + (seq * RH + k1_0) * P;
    #pragma unroll
    for (int r = 0; r < R2; r++) Xrow[r][t] = src[r * P + t];
    __syncthreads();

    // Stage 1 (conj w10)
    {
        const int b  = t / 10;
        const int rr = t - b * 10;
        float2 acc[R2];
        #pragma unroll
        for (int r = 0; r < R2; r++) acc[r] = make_float2(0.f, 0.f);
        int m = 0;
        #pragma unroll
        for (int a = 0; a < 10; a++) {
            float2 w = w10[m];
            m += rr; if (m >= 10) m -= 10;
            int si = 13 * a + b;
            #pragma unroll
            for (int r = 0; r < R2; r++) {
                float2 Xv = Xrow[r][si];
                acc[r].x = fmaf(Xv.x, w.x, acc[r].x);
                acc[r].x = fmaf(Xv.y, w.y, acc[r].x);
                acc[r].y = fmaf(Xv.y, w.x, acc[r].y);
                acc[r].y = fmaf(-Xv.x, w.y, acc[r].y);
            }
        }
        #pragma unroll
        for (int r = 0; r < R2; r++) G[r][t] = acc[r];
    }
    __syncthreads();

    // Stage 2 (conj tw130) + conj cross twiddle + Hermitian scale
    {
        const int n2 = t;
        const int r0 = n2 % 10;
        float2 acc[R2];
        #pragma unroll
        for (int r = 0; r < R2; r++) acc[r] = make_float2(0.f, 0.f);
        int idx = 0;
        #pragma unroll
        for (int b = 0; b < 13; b++) {
            float2 tt = tws[idx];
            idx += n2; if (idx >= P) idx -= P;
            int gi = b * 10 + r0;
            #pragma unroll
            for (int r = 0; r < R2; r++) {
                float2 Gv = G[r][gi];
                acc[r].x = fmaf(Gv.x, tt.x, acc[r].x);
                acc[r].x = fmaf(Gv.y, tt.y, acc[r].x);
                acc[r].y = fmaf(Gv.y, tt.x, acc[r].y);
                acc[r].y = fmaf(-Gv.x, tt.y, acc[r].y);
            }
        }
        float2* dst = g_buf1 + (seq * RH + k1_0) * P;
        #pragma unroll
        for (int r = 0; r < R2; r++) {
            int k1 = k1_0 + r;
            float2 T = g_twN[n2 * k1];     // apply conj(T)
            float sc = (k1 >= 1 && k1 <= 64) ? 2.0f : 1.0f;
            float2 c;
            c.x = (acc[r].x * T.x + acc[r].y * T.y) * sc;
            c.y = (acc[r].y * T.x - acc[r].x * T.y) * sc;
            dst[r * P + n2] = c;
        }
    }
}

// ---------------------------------------------------------------------------
// K4: inverse column FFT over k1 (folded: 66 terms), real part, scale 1/N
// x'[n1][n2] = (1/N) * sum_{k1=0..65} (C.re*t.re + C.im*t.im), t = tw130[(n1*k1)%130]
// grid (10, SEQ), block 130 (thread = n2), 13 n1 per block; k1-loop unrolled x2
// with float4 twiddle-pair loads.
#define NL4 13
__global__ void k_colifft() {
    __shared__ float2 twk[NL4][RH];          // twk[nl][k1] = tw130[(k1*(n1_0+nl))%130]
    const int seq  = blockIdx.y;
    const int n1_0 = blockIdx.x * NL4;
    const int n2   = threadIdx.x;

    if (n2 < RH) {
        #pragma unroll
        for (int nl = 0; nl < NL4; nl++) {
            int n1 = n1_0 + nl;
            twk[nl][n2] = g_tw130[(n2 * n1) % P];
        }
    }
    __syncthreads();

    float acc[NL4];
    #pragma unroll
    for (int nl = 0; nl < NL4; nl++) acc[nl] = 0.f;

    const float2* Crow = g_buf1 + seq * RH * P;
    for (int k1 = 0; k1 < RH; k1 += 2) {
        float2 Cv0 = Crow[k1 * P + n2];
        float2 Cv1 = Crow[(k1 + 1) * P + n2];
        #pragma unroll
        for (int nl = 0; nl < NL4; nl++) {
            float4 tp = *reinterpret_cast<const float4*>(&twk[nl][k1]);
            acc[nl] = fmaf(Cv0.x, tp.x, acc[nl]);
            acc[nl] = fmaf(Cv0.y, tp.y, acc[nl]);
            acc[nl] = fmaf(Cv1.x, tp.z, acc[nl]);
            acc[nl] = fmaf(Cv1.y, tp.w, acc[nl]);
        }
    }

    const float invN = 1.0f / (float)NTOT;
    #pragma unroll
    for (int nl = 0; nl < NL4; nl++) {
        int n1 = n1_0 + nl;
        g_xp[(seq * P + n1) * P + n2] = acc[nl] * invN;
    }
}

// ---------------------------------------------------------------------------
// K5: dense 3x3 cross-correlation on x' (valid on the 130x130 grid) + bias
__global__ void k_conv(const float* __restrict__ w,
                       const float* __restrict__ bias,
                       float* __restrict__ out) {
    __shared__ float rows[3][P];
    __shared__ float wsm[9][OCH];
    const int i = blockIdx.x;
    const int b = blockIdx.y;
    const int j = threadIdx.x;

    float acc[OCH];
    #pragma unroll
    for (int o = 0; o < OCH; o++) acc[o] = 0.f;

    for (int c = 0; c < CH; c++) {
        __syncthreads();
        const float* xp = g_xp + ((b * CH + c) * P + i) * P;
        for (int t = j; t < 3 * P; t += 128) {
            int r = t / P, col = t % P;
            rows[r][col] = xp[r * P + col];
        }
        for (int t = j; t < OCH * 9; t += 128) {
            int o = t / 9, rs = t % 9;
            wsm[rs][o] = w[(o * CH + c) * 9 + rs];
        }
        __syncthreads();

        float xv[9];
        #pragma unroll
        for (int r = 0; r < 3; r++)
            #pragma unroll
            for (int s = 0; s < 3; s++)
                xv[r * 3 + s] = rows[r][j + s];

        #pragma unroll
        for (int rs = 0; rs < 9; rs++) {
            float xr = xv[rs];
            #pragma unroll
            for (int og = 0; og < OCH / 4; og++) {
                float4 w4 = *reinterpret_cast<const float4*>(&wsm[rs][og * 4]);
                acc[og * 4 + 0] = fmaf(w4.x, xr, acc[og * 4 + 0]);
                acc[og * 4 + 1] = fmaf(w4.y, xr, acc[og * 4 + 1]);
                acc[og * 4 + 2] = fmaf(w4.z, xr, acc[og * 4 + 2]);
                acc[og * 4 + 3] = fmaf(w4.w, xr, acc[og * 4 + 3]);
            }
        }
    }

    #pragma unroll
    for (int o = 0; o < OCH; o++) {
        out[((b * OCH + o) * HH + i) * HH + j] = acc[o] + __ldg(&bias[o]);
    }
}

// ---------------------------------------------------------------------------
extern "C" void kernel_launch(void* const* d_in, const int* in_sizes, int n_in,
                              void* d_out, int out_size) {
    const float* x  = nullptr;
    const float* w  = nullptr;
    const float* bs = nullptr;
    for (int i = 0; i < n_in; i++) {
        if (in_sizes[i] == BATCH * CH * HH * HH)      x  = (const float*)d_in[i];
        else if (in_sizes[i] == OCH * CH * 3 * 3)     w  = (const float*)d_in[i];
        else if (in_sizes[i] == OCH)                  bs = (const float*)d_in[i];
    }
    float* out = (float*)d_out;

    k_init<<<(NTOT + 255) / 256, 256>>>();
    k_colfft<<<dim3(11, SEQ), P>>>(x);
    k_rowfft_thresh<<<dim3(11, SEQ), P>>>();
    k_rowifft<<<dim3(11, SEQ), P>>>();
    k_colifft<<<dim3(10, SEQ), P>>>();
    k_conv<<<dim3(HH, BATCH), HH>>>(w, bs, out);
}

// round 4
// speedup vs baseline: 3.9547x; 1.2573x over previous
#include <cuda_runtime.h>
#include <math.h>

// Problem constants
#define BATCH 4
#define CH    32
#define SEQ   (BATCH*CH)     // 128 independent length-N sequences
#define HH    128            // input H=W
#define P     130            // padded side (128 + 2*1)
#define NTOT  (P*P)          // 16900 = FFT length
#define OCH   32
#define RH    66             // Hermitian-half rows: k1 = 0..65

#define TWO_PI_F 6.2831853071795864769f

// Scratch (device globals; no allocation allowed)
__device__ float2 g_buf1[SEQ * RH * P];   // Bm (fwd), then Cm (post row-IFFT, rows 1..64 pre-scaled x2)
__device__ float  g_xp[SEQ * NTOT];       // x' (denoised padded image)

// ---------------------------------------------------------------------------
// K1: zero-pad + forward column FFT over n1 + cross twiddle. Rows k1=0..65 only.
// Bm[seq][k1][n2] = (sum_{n1=1..128} x[n1-1][n2-1] * tw130[(n1*k1)%130]) * twN[n2*k1]
// grid (3, SEQ), block 130 (thread = n2), 22 k1 per block; n1-loop unrolled x2
// with float4 twiddle-pair loads. Twiddles self-computed via sincosf.
#define KL1 22
__global__ void k_colfft(const float* __restrict__ x) {
    __shared__ float2 twk[KL1][128];         // twk[kl][i] = tw130[((i+1)*k1)%130]
    const int seq  = blockIdx.y;
    const int k1_0 = blockIdx.x * KL1;
    const int n2   = threadIdx.x;            // 0..129

    if (n2 < 128) {
        #pragma unroll
        for (int kl = 0; kl < KL1; kl++) {
            int k1 = k1_0 + kl;
            int m  = ((n2 + 1) * k1) % P;
            float s, c;
            __sincosf(0.f, &s, &c);          // placeholder to keep compiler honest (overwritten)
            sincosf((float)m * (-TWO_PI_F / (float)P), &s, &c);
            twk[kl][n2] = make_float2(c, s);
        }
    }
    __syncthreads();

    float2 acc[KL1];
    #pragma unroll
    for (int kl = 0; kl < KL1; kl++) acc[kl] = make_float2(0.f, 0.f);

    const float* xs = x + seq * HH * HH;
    const bool interior = (n2 >= 1 && n2 <= HH);

    for (int i = 0; i < 128; i += 2) {       // n1 = i+1, i+2
        float xv0 = interior ? __ldg(&xs[i * HH + (n2 - 1)]) : 0.f;
        float xv1 = interior ? __ldg(&xs[(i + 1) * HH + (n2 - 1)]) : 0.f;
        #pragma unroll
        for (int kl = 0; kl < KL1; kl++) {
            float4 tp = *reinterpret_cast<const float4*>(&twk[kl][i]);
            acc[kl].x = fmaf(xv0, tp.x, acc[kl].x);
            acc[kl].y = fmaf(xv0, tp.y, acc[kl].y);
            acc[kl].x = fmaf(xv1, tp.z, acc[kl].x);
            acc[kl].y = fmaf(xv1, tp.w, acc[kl].y);
        }
    }

    #pragma unroll
    for (int kl = 0; kl < KL1; kl++) {
        int k1 = k1_0 + kl;
        // T = twN[n2*k1], n2*k1 <= 129*65 < 16900
        float s, c;
        sincosf((float)(n2 * k1) * (-TWO_PI_F / (float)NTOT), &s, &c);
        float2 b;
        b.x = acc[kl].x * c - acc[kl].y * s;
        b.y = acc[kl].x * s + acc[kl].y * c;
        g_buf1[(seq * RH + k1) * P + n2] = b;
    }
}

// ---------------------------------------------------------------------------
// K2 (fused fwd+thresh+inv row FFT), radix 13x10 both directions.
// fwd:  n2 = 13a+b:  G[b][r] = sum_a B[13a+b] * w10[(a*r)%10]   (r = k2 mod 10)
//       X[k2] = sum_b G[b][k2%10] * tw130[(b*k2)%130];  threshold |Re|<0.01
// inv:  k2 = 13a+b:  G[b][r] = sum_a X[13a+b] * conj(w10[(a*r)%10])  (r = n2 mod 10)
//       Cm[n2] = (sum_b G[b][n2%10] * conj(tw130[(b*n2)%130])) * conj(twN[n2*k1])
// Rows 1..64 pre-scaled by 2 (Hermitian fold for K4).
// grid (11, SEQ), block 130, 6 rows per block
#define R2 6
__global__ void k_rowboth() {
    __shared__ float2 Brow[R2][P];   // input rows, then X
    __shared__ float2 G[R2][P];
    __shared__ float2 tws[P];
    __shared__ float2 w10[10];
    const int seq  = blockIdx.y;
    const int k1_0 = blockIdx.x * R2;
    const int t    = threadIdx.x;    // 0..129

    {
        float s, c;
        sincosf((float)t * (-TWO_PI_F / (float)P), &s, &c);
        tws[t] = make_float2(c, s);
        if (t < 10) {
            sincosf((float)t * (-TWO_PI_F / 10.f), &s, &c);
            w10[t] = make_float2(c, s);
        }
    }
    const float2* src = g_buf1 + (seq * RH + k1_0) * P;
    #pragma unroll
    for (int r = 0; r < R2; r++) Brow[r][t] = src[r * P + t];
    __syncthreads();

    const int bq = t / 10;           // 0..12
    const int rq = t - bq * 10;      // 0..9
    const int r0 = t % 10;

    // ---- fwd stage 1: Brow -> G
    {
        float2 acc[R2];
        #pragma unroll
        for (int r = 0; r < R2; r++) acc[r] = make_float2(0.f, 0.f);
        int m = 0;
        #pragma unroll
        for (int a = 0; a < 10; a++) {
            float2 w = w10[m];
            m += rq; if (m >= 10) m -= 10;
            int si = 13 * a + bq;
            #pragma unroll
            for (int r = 0; r < R2; r++) {
                float2 Bv = Brow[r][si];
                acc[r].x = fmaf(Bv.x, w.x, acc[r].x);
                acc[r].x = fmaf(-Bv.y, w.y, acc[r].x);
                acc[r].y = fmaf(Bv.x, w.y, acc[r].y);
                acc[r].y = fmaf(Bv.y, w.x, acc[r].y);
            }
        }
        __syncthreads();
        #pragma unroll
        for (int r = 0; r < R2; r++) G[r][t] = acc[r];
    }
    __syncthreads();

    // ---- fwd stage 2 + threshold: G -> Brow (X)
    {
        const int k2 = t;
        float2 acc[R2];
        #pragma unroll
        for (int r = 0; r < R2; r++) acc[r] = make_float2(0.f, 0.f);
        int idx = 0;
        #pragma unroll
        for (int b = 0; b < 13; b++) {
            float2 tt = tws[idx];
            idx += k2; if (idx >= P) idx -= P;
            int gi = b * 10 + r0;
            #pragma unroll
            for (int r = 0; r < R2; r++) {
                float2 Gv = G[r][gi];
                acc[r].x = fmaf(Gv.x, tt.x, acc[r].x);
                acc[r].x = fmaf(-Gv.y, tt.y, acc[r].x);
                acc[r].y = fmaf(Gv.x, tt.y, acc[r].y);
                acc[r].y = fmaf(Gv.y, tt.x, acc[r].y);
            }
        }
        __syncthreads();
        #pragma unroll
        for (int r = 0; r < R2; r++) {
            float2 v = acc[r];
            if (fabsf(v.x) < 0.01f) v = make_float2(0.f, 0.f);
            Brow[r][k2] = v;
        }
    }
    __syncthreads();

    // ---- inv stage 1 (conj w10): Brow(X) -> G
    {
        float2 acc[R2];
        #pragma unroll
        for (int r = 0; r < R2; r++) acc[r] = make_float2(0.f, 0.f);
        int m = 0;
        #pragma unroll
        for (int a = 0; a < 10; a++) {
            float2 w = w10[m];
            m += rq; if (m >= 10) m -= 10;
            int si = 13 * a + bq;
            #pragma unroll
            for (int r = 0; r < R2; r++) {
                float2 Xv = Brow[r][si];
                acc[r].x = fmaf(Xv.x, w.x, acc[r].x);
                acc[r].x = fmaf(Xv.y, w.y, acc[r].x);
                acc[r].y = fmaf(Xv.y, w.x, acc[r].y);
                acc[r].y = fmaf(-Xv.x, w.y, acc[r].y);
            }
        }
        __syncthreads();
        #pragma unroll
        for (int r = 0; r < R2; r++) G[r][t] = acc[r];
    }
    __syncthreads();

    // ---- inv stage 2 (conj tws) + conj cross twiddle + Hermitian scale -> global
    {
        const int n2 = t;
        float2 acc[R2];
        #pragma unroll
        for (int r = 0; r < R2; r++) acc[r] = make_float2(0.f, 0.f);
        int idx = 0;
        #pragma unroll
        for (int b = 0; b < 13; b++) {
            float2 tt = tws[idx];
            idx += n2; if (idx >= P) idx -= P;
            int gi = b * 10 + r0;
            #pragma unroll
            for (int r = 0; r < R2; r++) {
                float2 Gv = G[r][gi];
                acc[r].x = fmaf(Gv.x, tt.x, acc[r].x);
                acc[r].x = fmaf(Gv.y, tt.y, acc[r].x);
                acc[r].y = fmaf(Gv.y, tt.x, acc[r].y);
                acc[r].y = fmaf(-Gv.x, tt.y, acc[r].y);
            }
        }
        float2* dst = g_buf1 + (seq * RH + k1_0) * P;
        #pragma unroll
        for (int r = 0; r < R2; r++) {
            int k1 = k1_0 + r;
            float s, c;
            sincosf((float)(n2 * k1) * (-TWO_PI_F / (float)NTOT), &s, &c);
            float sc = (k1 >= 1 && k1 <= 64) ? 2.0f : 1.0f;
            float2 cm;  // acc * conj(T) * sc
            cm.x = (acc[r].x * c + acc[r].y * s) * sc;
            cm.y = (acc[r].y * c - acc[r].x * s) * sc;
            dst[r * P + n2] = cm;
        }
    }
}

// ---------------------------------------------------------------------------
// K4: inverse column FFT over k1 (folded: 66 terms), real part, scale 1/N
// x'[n1][n2] = (1/N) * sum_{k1=0..65} (C.re*t.re + C.im*t.im), t = tw130[(n1*k1)%130]
// grid (5, SEQ), block 130 (thread = n2), 26 n1 per block; k1-loop unrolled x2.
#define NL4 26
__global__ void k_colifft() {
    __shared__ float2 twk[NL4][RH];          // twk[nl][k1] = tw130[(k1*(n1_0+nl))%130]
    const int seq  = blockIdx.y;
    const int n1_0 = blockIdx.x * NL4;
    const int n2   = threadIdx.x;

    if (n2 < RH) {
        #pragma unroll
        for (int nl = 0; nl < NL4; nl++) {
            int n1 = n1_0 + nl;
            int m  = (n2 * n1) % P;
            float s, c;
            sincosf((float)m * (-TWO_PI_F / (float)P), &s, &c);
            twk[nl][n2] = make_float2(c, s);
        }
    }
    __syncthreads();

    float acc[NL4];
    #pragma unroll
    for (int nl = 0; nl < NL4; nl++) acc[nl] = 0.f;

    const float2* Crow = g_buf1 + seq * RH * P;
    for (int k1 = 0; k1 < RH; k1 += 2) {
        float2 Cv0 = Crow[k1 * P + n2];
        float2 Cv1 = Crow[(k1 + 1) * P + n2];
        #pragma unroll
        for (int nl = 0; nl < NL4; nl++) {
            float4 tp = *reinterpret_cast<const float4*>(&twk[nl][k1]);
            acc[nl] = fmaf(Cv0.x, tp.x, acc[nl]);
            acc[nl] = fmaf(Cv0.y, tp.y, acc[nl]);
            acc[nl] = fmaf(Cv1.x, tp.z, acc[nl]);
            acc[nl] = fmaf(Cv1.y, tp.w, acc[nl]);
        }
    }

    const float invN = 1.0f / (float)NTOT;
    #pragma unroll
    for (int nl = 0; nl < NL4; nl++) {
        int n1 = n1_0 + nl;
        g_xp[(seq * P + n1) * P + n2] = acc[nl] * invN;
    }
}

// ---------------------------------------------------------------------------
// K5: dense 3x3 cross-correlation on x' (valid on the 130x130 grid) + bias.
// grid (64 i-pairs, 4 b, 2 o-halves), block 128 (thread = j).
// Each thread computes 2 output rows x 16 output channels.
// Weights for the o-half preloaded once; rows double-buffered, 1 sync/channel.
__global__ void k_conv(const float* __restrict__ w,
                       const float* __restrict__ bias,
                       float* __restrict__ out) {
    __shared__ float wsm[CH][9][16];        // [c][rs][o'] for this o-half (18KB)
    __shared__ float rows[2][4][P];         // double-buffered 4 input rows
    const int i0 = blockIdx.x * 2;
    const int b  = blockIdx.y;
    const int oh = blockIdx.z;
    const int j  = threadIdx.x;

    // Preload all weights for this o-half
    for (int t = j; t < 16 * CH * 9; t += 128) {
        int oo  = t / (CH * 9);
        int rem = t - oo * (CH * 9);
        int c   = rem / 9;
        int rs  = rem - c * 9;
        wsm[c][rs][oo] = w[((oh * 16 + oo) * CH + c) * 9 + rs];
    }

    float acc[2][16];
    #pragma unroll
    for (int ri = 0; ri < 2; ri++)
        #pragma unroll
        for (int o = 0; o < 16; o++) acc[ri][o] = 0.f;

    // First rows load for c=0 happens inside the loop; need weights visible
    __syncthreads();

    for (int c = 0; c < CH; c++) {
        int buf = c & 1;
        const float* xp = g_xp + ((b * CH + c) * P + i0) * P;
        for (int t = j; t < 4 * P; t += 128) {
            int r = t / P, col = t - r * P;
            rows[buf][r][col] = xp[r * P + col];
        }
        __syncthreads();

        float xq[4][3];
        #pragma unroll
        for (int r = 0; r < 4; r++)
            #pragma unroll
            for (int s = 0; s < 3; s++)
                xq[r][s] = rows[buf][r][j + s];

        #pragma unroll
        for (int r = 0; r < 3; r++) {
            #pragma unroll
            for (int s = 0; s < 3; s++) {
                #pragma unroll
                for (int og = 0; og < 4; og++) {
                    float4 w4 = *reinterpret_cast<const float4*>(&wsm[c][r * 3 + s][og * 4]);
                    #pragma unroll
                    for (int ri = 0; ri < 2; ri++) {
                        float xv = xq[ri + r][s];
                        acc[ri][og * 4 + 0] = fmaf(w4.x, xv, acc[ri][og * 4 + 0]);
                        acc[ri][og * 4 + 1] = fmaf(w4.y, xv, acc[ri][og * 4 + 1]);
                        acc[ri][og * 4 + 2] = fmaf(w4.z, xv, acc[ri][og * 4 + 2]);
                        acc[ri][og * 4 + 3] = fmaf(w4.w, xv, acc[ri][og * 4 + 3]);
                    }
                }
            }
        }
    }

    #pragma unroll
    for (int ri = 0; ri < 2; ri++) {
        #pragma unroll
        for (int oo = 0; oo < 16; oo++) {
            int o = oh * 16 + oo;
            out[((b * OCH + o) * HH + (i0 + ri)) * HH + j] = acc[ri][oo] + __ldg(&bias[o]);
        }
    }
}

// ---------------------------------------------------------------------------
extern "C" void kernel_launch(void* const* d_in, const int* in_sizes, int n_in,
                              void* d_out, int out_size) {
    const float* x  = nullptr;
    const float* w  = nullptr;
    const float* bs = nullptr;
    for (int i = 0; i < n_in; i++) {
        if (in_sizes[i] == BATCH * CH * HH * HH)      x  = (const float*)d_in[i];
        else if (in_sizes[i] == OCH * CH * 3 * 3)     w  = (const float*)d_in[i];
        else if (in_sizes[i] == OCH)                  bs = (const float*)d_in[i];
    }
    float* out = (float*)d_out;

    k_colfft<<<dim3(3, SEQ), P>>>(x);
    k_rowboth<<<dim3(11, SEQ), P>>>();
    k_colifft<<<dim3(5, SEQ), P>>>();
    k_conv<<<dim3(HH / 2, BATCH, 2), 128>>>(w, bs, out);
}

// round 5
// speedup vs baseline: 3.9770x; 1.0056x over previous
#include <cuda_runtime.h>
#include <math.h>

// Problem constants
#define BATCH 4
#define CH    32
#define SEQ   (BATCH*CH)     // 128 independent length-N sequences
#define HH    128            // input H=W
#define P     130            // padded side (128 + 2*1)
#define NTOT  (P*P)          // 16900 = FFT length
#define OCH   32
#define RH    66             // Hermitian-half rows: k1 = 0..65

#define TWO_PI_F 6.2831853071795864769f

// Scratch (device globals; no allocation allowed)
__device__ float2 g_buf1[SEQ * RH * P];   // Bm (fwd), then Cm (post row-IFFT, rows 1..64 pre-scaled x2)
__device__ float  g_xp[SEQ * NTOT];       // x' (denoised padded image)

// ---------------------------------------------------------------------------
// K1: zero-pad + forward column FFT over n1 + cross twiddle. Rows k1=0..65 only.
// Bm[seq][k1][n2] = (sum_{n1=1..128} x[n1-1][n2-1] * tw130[(n1*k1)%130]) * twN[n2*k1]
// grid (3, SEQ), block 130 (thread = n2), 22 k1 per block; n1-loop unrolled x2
// with float4 twiddle-pair loads. Twiddles self-computed via sincosf.
#define KL1 22
__global__ void k_colfft(const float* __restrict__ x) {
    __shared__ float2 twk[KL1][128];         // twk[kl][i] = tw130[((i+1)*k1)%130]
    const int seq  = blockIdx.y;
    const int k1_0 = blockIdx.x * KL1;
    const int n2   = threadIdx.x;            // 0..129

    if (n2 < 128) {
        #pragma unroll
        for (int kl = 0; kl < KL1; kl++) {
            int k1 = k1_0 + kl;
            int m  = ((n2 + 1) * k1) % P;
            float s, c;
            sincosf((float)m * (-TWO_PI_F / (float)P), &s, &c);
            twk[kl][n2] = make_float2(c, s);
        }
    }
    __syncthreads();

    float2 acc[KL1];
    #pragma unroll
    for (int kl = 0; kl < KL1; kl++) acc[kl] = make_float2(0.f, 0.f);

    const float* xs = x + seq * HH * HH;
    const bool interior = (n2 >= 1 && n2 <= HH);

    for (int i = 0; i < 128; i += 2) {       // n1 = i+1, i+2
        float xv0 = interior ? __ldg(&xs[i * HH + (n2 - 1)]) : 0.f;
        float xv1 = interior ? __ldg(&xs[(i + 1) * HH + (n2 - 1)]) : 0.f;
        #pragma unroll
        for (int kl = 0; kl < KL1; kl++) {
            float4 tp = *reinterpret_cast<const float4*>(&twk[kl][i]);
            acc[kl].x = fmaf(xv0, tp.x, acc[kl].x);
            acc[kl].y = fmaf(xv0, tp.y, acc[kl].y);
            acc[kl].x = fmaf(xv1, tp.z, acc[kl].x);
            acc[kl].y = fmaf(xv1, tp.w, acc[kl].y);
        }
    }

    #pragma unroll
    for (int kl = 0; kl < KL1; kl++) {
        int k1 = k1_0 + kl;
        // T = twN[n2*k1], n2*k1 <= 129*65 < 16900
        float s, c;
        sincosf((float)(n2 * k1) * (-TWO_PI_F / (float)NTOT), &s, &c);
        float2 b;
        b.x = acc[kl].x * c - acc[kl].y * s;
        b.y = acc[kl].x * s + acc[kl].y * c;
        g_buf1[(seq * RH + k1) * P + n2] = b;
    }
}

// ---------------------------------------------------------------------------
// K2 (fused fwd+thresh+inv row FFT), radix 13x10 both directions.
// grid (11, SEQ), block 130, 6 rows per block
#define R2 6
__global__ void k_rowboth() {
    __shared__ float2 Brow[R2][P];   // input rows, then X
    __shared__ float2 G[R2][P];
    __shared__ float2 tws[P];
    __shared__ float2 w10[10];
    const int seq  = blockIdx.y;
    const int k1_0 = blockIdx.x * R2;
    const int t    = threadIdx.x;    // 0..129

    {
        float s, c;
        sincosf((float)t * (-TWO_PI_F / (float)P), &s, &c);
        tws[t] = make_float2(c, s);
        if (t < 10) {
            sincosf((float)t * (-TWO_PI_F / 10.f), &s, &c);
            w10[t] = make_float2(c, s);
        }
    }
    const float2* src = g_buf1 + (seq * RH + k1_0) * P;
    #pragma unroll
    for (int r = 0; r < R2; r++) Brow[r][t] = src[r * P + t];
    __syncthreads();

    const int bq = t / 10;           // 0..12
    const int rq = t - bq * 10;      // 0..9
    const int r0 = t % 10;

    // ---- fwd stage 1: Brow -> G
    {
        float2 acc[R2];
        #pragma unroll
        for (int r = 0; r < R2; r++) acc[r] = make_float2(0.f, 0.f);
        int m = 0;
        #pragma unroll
        for (int a = 0; a < 10; a++) {
            float2 w = w10[m];
            m += rq; if (m >= 10) m -= 10;
            int si = 13 * a + bq;
            #pragma unroll
            for (int r = 0; r < R2; r++) {
                float2 Bv = Brow[r][si];
                acc[r].x = fmaf(Bv.x, w.x, acc[r].x);
                acc[r].x = fmaf(-Bv.y, w.y, acc[r].x);
                acc[r].y = fmaf(Bv.x, w.y, acc[r].y);
                acc[r].y = fmaf(Bv.y, w.x, acc[r].y);
            }
        }
        __syncthreads();
        #pragma unroll
        for (int r = 0; r < R2; r++) G[r][t] = acc[r];
    }
    __syncthreads();

    // ---- fwd stage 2 + threshold: G -> Brow (X)
    {
        const int k2 = t;
        float2 acc[R2];
        #pragma unroll
        for (int r = 0; r < R2; r++) acc[r] = make_float2(0.f, 0.f);
        int idx = 0;
        #pragma unroll
        for (int b = 0; b < 13; b++) {
            float2 tt = tws[idx];
            idx += k2; if (idx >= P) idx -= P;
            int gi = b * 10 + r0;
            #pragma unroll
            for (int r = 0; r < R2; r++) {
                float2 Gv = G[r][gi];
                acc[r].x = fmaf(Gv.x, tt.x, acc[r].x);
                acc[r].x = fmaf(-Gv.y, tt.y, acc[r].x);
                acc[r].y = fmaf(Gv.x, tt.y, acc[r].y);
                acc[r].y = fmaf(Gv.y, tt.x, acc[r].y);
            }
        }
        __syncthreads();
        #pragma unroll
        for (int r = 0; r < R2; r++) {
            float2 v = acc[r];
            if (fabsf(v.x) < 0.01f) v = make_float2(0.f, 0.f);
            Brow[r][k2] = v;
        }
    }
    __syncthreads();

    // ---- inv stage 1 (conj w10): Brow(X) -> G
    {
        float2 acc[R2];
        #pragma unroll
        for (int r = 0; r < R2; r++) acc[r] = make_float2(0.f, 0.f);
        int m = 0;
        #pragma unroll
        for (int a = 0; a < 10; a++) {
            float2 w = w10[m];
            m += rq; if (m >= 10) m -= 10;
            int si = 13 * a + bq;
            #pragma unroll
            for (int r = 0; r < R2; r++) {
                float2 Xv = Brow[r][si];
                acc[r].x = fmaf(Xv.x, w.x, acc[r].x);
                acc[r].x = fmaf(Xv.y, w.y, acc[r].x);
                acc[r].y = fmaf(Xv.y, w.x, acc[r].y);
                acc[r].y = fmaf(-Xv.x, w.y, acc[r].y);
            }
        }
        __syncthreads();
        #pragma unroll
        for (int r = 0; r < R2; r++) G[r][t] = acc[r];
    }
    __syncthreads();

    // ---- inv stage 2 (conj tws) + conj cross twiddle + Hermitian scale -> global
    {
        const int n2 = t;
        float2 acc[R2];
        #pragma unroll
        for (int r = 0; r < R2; r++) acc[r] = make_float2(0.f, 0.f);
        int idx = 0;
        #pragma unroll
        for (int b = 0; b < 13; b++) {
            float2 tt = tws[idx];
            idx += n2; if (idx >= P) idx -= P;
            int gi = b * 10 + r0;
            #pragma unroll
            for (int r = 0; r < R2; r++) {
                float2 Gv = G[r][gi];
                acc[r].x = fmaf(Gv.x, tt.x, acc[r].x);
                acc[r].x = fmaf(Gv.y, tt.y, acc[r].x);
                acc[r].y = fmaf(Gv.y, tt.x, acc[r].y);
                acc[r].y = fmaf(-Gv.x, tt.y, acc[r].y);
            }
        }
        float2* dst = g_buf1 + (seq * RH + k1_0) * P;
        #pragma unroll
        for (int r = 0; r < R2; r++) {
            int k1 = k1_0 + r;
            float s, c;
            sincosf((float)(n2 * k1) * (-TWO_PI_F / (float)NTOT), &s, &c);
            float sc = (k1 >= 1 && k1 <= 64) ? 2.0f : 1.0f;
            float2 cm;  // acc * conj(T) * sc
            cm.x = (acc[r].x * c + acc[r].y * s) * sc;
            cm.y = (acc[r].y * c - acc[r].x * s) * sc;
            dst[r * P + n2] = cm;
        }
    }
}

// ---------------------------------------------------------------------------
// K4: inverse column FFT over k1 (folded: 66 terms), real part, scale 1/N
// grid (5, SEQ), block 130 (thread = n2), 26 n1 per block; k1-loop unrolled x2.
#define NL4 26
__global__ void k_colifft() {
    __shared__ float2 twk[NL4][RH];          // twk[nl][k1] = tw130[(k1*(n1_0+nl))%130]
    const int seq  = blockIdx.y;
    const int n1_0 = blockIdx.x * NL4;
    const int n2   = threadIdx.x;

    if (n2 < RH) {
        #pragma unroll
        for (int nl = 0; nl < NL4; nl++) {
            int n1 = n1_0 + nl;
            int m  = (n2 * n1) % P;
            float s, c;
            sincosf((float)m * (-TWO_PI_F / (float)P), &s, &c);
            twk[nl][n2] = make_float2(c, s);
        }
    }
    __syncthreads();

    float acc[NL4];
    #pragma unroll
    for (int nl = 0; nl < NL4; nl++) acc[nl] = 0.f;

    const float2* Crow = g_buf1 + seq * RH * P;
    for (int k1 = 0; k1 < RH; k1 += 2) {
        float2 Cv0 = Crow[k1 * P + n2];
        float2 Cv1 = Crow[(k1 + 1) * P + n2];
        #pragma unroll
        for (int nl = 0; nl < NL4; nl++) {
            float4 tp = *reinterpret_cast<const float4*>(&twk[nl][k1]);
            acc[nl] = fmaf(Cv0.x, tp.x, acc[nl]);
            acc[nl] = fmaf(Cv0.y, tp.y, acc[nl]);
            acc[nl] = fmaf(Cv1.x, tp.z, acc[nl]);
            acc[nl] = fmaf(Cv1.y, tp.w, acc[nl]);
        }
    }

    const float invN = 1.0f / (float)NTOT;
    #pragma unroll
    for (int nl = 0; nl < NL4; nl++) {
        int n1 = n1_0 + nl;
        g_xp[(seq * P + n1) * P + n2] = acc[nl] * invN;
    }
}

// ---------------------------------------------------------------------------
// K5: dense 3x3 cross-correlation on x' (valid on the 130x130 grid) + bias.
// grid (128 rows, 4 b, 2 o-halves), block 128 (thread = j).
// 1 output row per block, 16 output channels per thread.
// Channels loaded in PAIRS (one sync per 2 channels), double-buffered.
__global__ void __launch_bounds__(128) k_conv(const float* __restrict__ w,
                       const float* __restrict__ bias,
                       float* __restrict__ out) {
    __shared__ float wsm[CH][9][16];         // [c][rs][o'] for this o-half (18KB)
    __shared__ float rows[2][2][3][132];     // [buf][ch-in-pair][r][col] (12.7KB)
    const int i  = blockIdx.x;               // output row
    const int b  = blockIdx.y;
    const int oh = blockIdx.z;
    const int j  = threadIdx.x;

    // Preload all weights for this o-half
    for (int t = j; t < 16 * CH * 9; t += 128) {
        int oo  = t / (CH * 9);
        int rem = t - oo * (CH * 9);
        int c   = rem / 9;
        int rs  = rem - c * 9;
        wsm[c][rs][oo] = w[((oh * 16 + oo) * CH + c) * 9 + rs];
    }

    float acc[16];
    #pragma unroll
    for (int o = 0; o < 16; o++) acc[o] = 0.f;

    __syncthreads();   // weights visible

    for (int cp = 0; cp < CH / 2; cp++) {
        const int buf = cp & 1;
        // Load rows i..i+2 for channels 2cp and 2cp+1
        const float* xp0 = g_xp + ((b * CH + 2 * cp) * P + i) * P;
        for (int t = j; t < 2 * 3 * P; t += 128) {
            int cc  = t / (3 * P);
            int rem = t - cc * (3 * P);
            int r   = rem / P;
            int col = rem - r * P;
            rows[buf][cc][r][col] = xp0[cc * NTOT + r * P + col];
        }
        __syncthreads();   // safe: double-buffered (see analysis)

        #pragma unroll
        for (int ci = 0; ci < 2; ci++) {
            const int c = 2 * cp + ci;
            float xq[3][3];
            #pragma unroll
            for (int r = 0; r < 3; r++)
                #pragma unroll
                for (int s = 0; s < 3; s++)
                    xq[r][s] = rows[buf][ci][r][j + s];

            #pragma unroll
            for (int r = 0; r < 3; r++) {
                #pragma unroll
                for (int s = 0; s < 3; s++) {
                    float xv = xq[r][s];
                    #pragma unroll
                    for (int og = 0; og < 4; og++) {
                        float4 w4 = *reinterpret_cast<const float4*>(&wsm[c][r * 3 + s][og * 4]);
                        acc[og * 4 + 0] = fmaf(w4.x, xv, acc[og * 4 + 0]);
                        acc[og * 4 + 1] = fmaf(w4.y, xv, acc[og * 4 + 1]);
                        acc[og * 4 + 2] = fmaf(w4.z, xv, acc[og * 4 + 2]);
                        acc[og * 4 + 3] = fmaf(w4.w, xv, acc[og * 4 + 3]);
                    }
                }
            }
        }
    }

    #pragma unroll
    for (int oo = 0; oo < 16; oo++) {
        int o = oh * 16 + oo;
        out[((b * OCH + o) * HH + i) * HH + j] = acc[oo] + __ldg(&bias[o]);
    }
}

// ---------------------------------------------------------------------------
extern "C" void kernel_launch(void* const* d_in, const int* in_sizes, int n_in,
                              void* d_out, int out_size) {
    const float* x  = nullptr;
    const float* w  = nullptr;
    const float* bs = nullptr;
    for (int i = 0; i < n_in; i++) {
        if (in_sizes[i] == BATCH * CH * HH * HH)      x  = (const float*)d_in[i];
        else if (in_sizes[i] == OCH * CH * 3 * 3)     w  = (const float*)d_in[i];
        else if (in_sizes[i] == OCH)                  bs = (const float*)d_in[i];
    }
    float* out = (float*)d_out;

    k_colfft<<<dim3(3, SEQ), P>>>(x);
    k_rowboth<<<dim3(11, SEQ), P>>>();
    k_colifft<<<dim3(5, SEQ), P>>>();
    k_conv<<<dim3(HH, BATCH, 2), 128>>>(w, bs, out);
}